// round 11
// baseline (speedup 1.0000x reference)
#include <cuda_runtime.h>
#include <cuda_bf16.h>
#include <cuda_fp16.h>
#include <math.h>
#include <stdint.h>

// ---------------- problem constants ----------------
#define D_MODEL 256
#define D_FFN   1024
#define LQ      21760
#define BATCH   2
#define M_ROWS  (BATCH * LQ)   // 43520

__device__ __constant__ int c_ST[4] = {0, 16384, 20480, 21504};

// ---------------- scratch ----------------
__device__ __nv_bfloat16 g_srcb [(size_t)M_ROWS * D_MODEL];
__device__ __nv_bfloat16 g_qsumb[(size_t)M_ROWS * D_MODEL];
__device__ __nv_bfloat16 g_value[(size_t)M_ROWS * D_MODEL];
__device__ float g_oa   [(size_t)M_ROWS * 384];
__device__ __nv_bfloat16 g_samp [(size_t)M_ROWS * D_MODEL];
__device__ float g_h    [(size_t)M_ROWS * D_MODEL];
__device__ __nv_bfloat16 g_hb   [(size_t)M_ROWS * D_MODEL];
__device__ __nv_bfloat16 g_ffn  [(size_t)M_ROWS * D_FFN];
__device__ __nv_bfloat16 g_WvalT [256 * 256];
__device__ __nv_bfloat16 g_WoaT  [384 * 256];
__device__ __nv_bfloat16 g_WoutT [256 * 256];
__device__ __nv_bfloat16 g_W1T   [1024 * 256];
__device__ __nv_bfloat16 g_W2T   [256 * 1024];

// ---------------- helpers ----------------
__device__ __forceinline__ uint32_t smem_u32(const void* p) {
    uint32_t a;
    asm("{ .reg .u64 t; cvta.to.shared.u64 t, %1; cvt.u32.u64 %0, t; }" : "=r"(a) : "l"(p));
    return a;
}
__device__ __forceinline__ void cpasync16(uint32_t dst, const void* src) {
    asm volatile("cp.async.cg.shared.global [%0], [%1], 16;" :: "r"(dst), "l"(src));
}
__device__ __forceinline__ void ldsm_x4(uint32_t& r0, uint32_t& r1, uint32_t& r2, uint32_t& r3, uint32_t addr) {
    asm volatile("ldmatrix.sync.aligned.m8n8.x4.shared.b16 {%0,%1,%2,%3}, [%4];"
        : "=r"(r0), "=r"(r1), "=r"(r2), "=r"(r3) : "r"(addr));
}
__device__ __forceinline__ void mma_bf16(float* d, const uint32_t* a, const uint32_t* b) {
    asm volatile("mma.sync.aligned.m16n8k16.row.col.f32.bf16.bf16.f32 "
        "{%0,%1,%2,%3}, {%4,%5,%6,%7}, {%8,%9}, {%0,%1,%2,%3};"
        : "+f"(d[0]), "+f"(d[1]), "+f"(d[2]), "+f"(d[3])
        : "r"(a[0]), "r"(a[1]), "r"(a[2]), "r"(a[3]), "r"(b[0]), "r"(b[1]));
}

// ---------------- shared GEMM core: 128x128 tile, BK=64, 3-stage ----------------
__device__ __forceinline__ void gemm_core(
    const __nv_bfloat16* __restrict__ A, const __nv_bfloat16* __restrict__ WT,
    const float* __restrict__ bias, const float* __restrict__ bias2, int nsplit,
    const float* __restrict__ res, void* __restrict__ Cout,
    bool relu, bool bf16out, int N, int K, int bm, int bn, uint32_t smBase)
{
    const int tid = threadIdx.x;
    const int lane = tid & 31;
    const int wid = tid >> 5;
    const int wm = wid & 1;
    const int wn = wid >> 1;

    const __nv_bfloat16* aG[4]; const __nv_bfloat16* bG[4];
    uint32_t sOff[4];
#pragma unroll
    for (int i = 0; i < 4; i++) {
        const int id = tid + i * 256;
        const int row = id >> 3, ck = id & 7;
        aG[i] = A  + (size_t)(bm + row) * K + ck * 8;
        bG[i] = WT + (size_t)(bn + row) * K + ck * 8;
        sOff[i] = row * 128 + ((ck ^ (row & 7)) * 16);
    }

    const int aRow = wm * 64 + (lane & 15);
    const int aCkH = lane >> 4;
    const int bRow = wn * 32 + ((lane >> 4) & 1) * 8 + (lane & 7);
    const int bCkH = (lane >> 3) & 1;

    float acc[4][4][4];
#pragma unroll
    for (int i = 0; i < 4; i++)
#pragma unroll
        for (int j = 0; j < 4; j++)
#pragma unroll
            for (int k = 0; k < 4; k++) acc[i][j][k] = 0.f;

    const int Cs = K >> 6;

#pragma unroll
    for (int i = 0; i < 4; i++) {
        cpasync16(smBase + sOff[i], aG[i]);
        cpasync16(smBase + 16384 + sOff[i], bG[i]);
    }
    asm volatile("cp.async.commit_group;" ::: "memory");
#pragma unroll
    for (int i = 0; i < 4; i++) {
        cpasync16(smBase + 32768 + sOff[i], aG[i] + 64);
        cpasync16(smBase + 32768 + 16384 + sOff[i], bG[i] + 64);
    }
    asm volatile("cp.async.commit_group;" ::: "memory");

    int st = 0, ldst = 2;
    for (int c = 0; c < Cs; ++c) {
        if (c == Cs - 1) asm volatile("cp.async.wait_group 0;" ::: "memory");
        else             asm volatile("cp.async.wait_group 1;" ::: "memory");
        __syncthreads();

        const uint32_t sA = smBase + (uint32_t)st * 32768;
        const uint32_t sB = sA + 16384;

#pragma unroll
        for (int ks = 0; ks < 4; ks++) {
            uint32_t af[4][4];
            uint32_t bfr[2][4];
#pragma unroll
            for (int mt = 0; mt < 4; mt++) {
                const int row = aRow + mt * 16;
                const int ck = ks * 2 + aCkH;
                ldsm_x4(af[mt][0], af[mt][1], af[mt][2], af[mt][3],
                        sA + row * 128 + ((ck ^ (row & 7)) * 16));
            }
#pragma unroll
            for (int np = 0; np < 2; np++) {
                const int row = bRow + np * 16;
                const int ck = ks * 2 + bCkH;
                ldsm_x4(bfr[np][0], bfr[np][1], bfr[np][2], bfr[np][3],
                        sB + row * 128 + ((ck ^ (row & 7)) * 16));
            }
#pragma unroll
            for (int mt = 0; mt < 4; mt++)
#pragma unroll
                for (int nt = 0; nt < 4; nt++)
                    mma_bf16(acc[mt][nt], af[mt], &bfr[nt >> 1][(nt & 1) * 2]);
        }

        if (c + 2 < Cs) {
            const int k0 = (c + 2) << 6;
            const uint32_t dA = smBase + (uint32_t)ldst * 32768;
#pragma unroll
            for (int i = 0; i < 4; i++) {
                cpasync16(dA + sOff[i], aG[i] + k0);
                cpasync16(dA + 16384 + sOff[i], bG[i] + k0);
            }
            asm volatile("cp.async.commit_group;" ::: "memory");
        }
        st = (st == 2) ? 0 : st + 1;
        ldst = (ldst == 2) ? 0 : ldst + 1;
    }

    const int r0base = bm + wm * 64 + (lane >> 2);
    const int cbase  = bn + wn * 32 + (lane & 3) * 2;
#pragma unroll
    for (int mt = 0; mt < 4; mt++) {
#pragma unroll
        for (int nt = 0; nt < 4; nt++) {
            const int col = cbase + nt * 8;
            const float bx = (col < nsplit) ? bias[col] : bias2[col - nsplit];
            const float by = (col + 1 < nsplit) ? bias[col + 1] : bias2[col + 1 - nsplit];
#pragma unroll
            for (int half = 0; half < 2; half++) {
                const int row = r0base + mt * 16 + half * 8;
                float vx = acc[mt][nt][half * 2 + 0] + bx;
                float vy = acc[mt][nt][half * 2 + 1] + by;
                if (res) {
                    const float* rp = res + (size_t)row * N + col;
                    vx += rp[0]; vy += rp[1];
                }
                if (relu) { vx = fmaxf(vx, 0.f); vy = fmaxf(vy, 0.f); }
                if (bf16out) {
                    __nv_bfloat162 bb = __floats2bfloat162_rn(vx, vy);
                    *(__nv_bfloat162*)((__nv_bfloat16*)Cout + (size_t)row * N + col) = bb;
                } else {
                    *(float2*)((float*)Cout + (size_t)row * N + col) = make_float2(vx, vy);
                }
            }
        }
    }
}

// merged value + oa projection GEMM: grid (5, MT). bx<2 -> value, else oa.
__global__ void __launch_bounds__(256) gemm_proj(
    const __nv_bfloat16* __restrict__ srcb, const __nv_bfloat16* __restrict__ qsumb,
    const __nv_bfloat16* __restrict__ WvalT, const __nv_bfloat16* __restrict__ WoaT,
    const float* __restrict__ b_val, const float* __restrict__ b_off,
    const float* __restrict__ b_attn,
    __nv_bfloat16* __restrict__ value, float* __restrict__ oa)
{
    extern __shared__ char dynsm[];
    const uint32_t smBase = smem_u32(dynsm);
    const int bm = blockIdx.y * 128;
    const bool isVal = blockIdx.x < 2;
    if (isVal) {
        gemm_core(srcb, WvalT, b_val, b_val, 1 << 30, nullptr, value,
                  false, true, 256, 256, bm, blockIdx.x * 128, smBase);
    } else {
        gemm_core(qsumb, WoaT, b_off, b_attn, 256, nullptr, oa,
                  false, false, 384, 256, bm, (blockIdx.x - 2) * 128, smBase);
    }
}

// ffn GEMM: relu + bf16 out
__global__ void __launch_bounds__(256) gemm_ffn(
    const __nv_bfloat16* __restrict__ hb, const __nv_bfloat16* __restrict__ W1T,
    const float* __restrict__ b1, __nv_bfloat16* __restrict__ ffn)
{
    extern __shared__ char dynsm[];
    const uint32_t smBase = smem_u32(dynsm);
    gemm_core(hb, W1T, b1, b1, 1 << 30, nullptr, ffn,
              true, true, 1024, 256, blockIdx.y * 128, blockIdx.x * 128, smBase);
}

// ---------------- fused GEMM (64x256 tile) + residual + LayerNorm ----------------
// C = A[M,K] @ W[K,256] + bias + res; out = LN(C) (fp32, + optional bf16 copy).
// 8 warps 2m x 4n, warp tile 32x64. 2-stage (double-sync). Stage = A 8KB + B 32KB.
__global__ void __launch_bounds__(256, 2) gemm_ln(
    const __nv_bfloat16* __restrict__ A, const __nv_bfloat16* __restrict__ WT,
    const float* __restrict__ bias, const float* __restrict__ res,
    const float* __restrict__ gamma, const float* __restrict__ beta,
    float* __restrict__ outF, __nv_bfloat16* __restrict__ outB, int K)
{
    extern __shared__ char dynsm[];
    const uint32_t smBase = smem_u32(dynsm);
    float* smF = (float*)dynsm;

    const int tid = threadIdx.x;
    const int lane = tid & 31;
    const int wid = tid >> 5;
    const int wm = wid & 1;
    const int wn = wid >> 1;
    const int bm = blockIdx.x * 64;

    // loaders: A 512 chunks (2/thr), B 2048 chunks (8/thr)
    const __nv_bfloat16* aG[2]; uint32_t aOff[2];
#pragma unroll
    for (int i = 0; i < 2; i++) {
        const int id = tid + i * 256;
        const int row = id >> 3, ck = id & 7;
        aG[i] = A + (size_t)(bm + row) * K + ck * 8;
        aOff[i] = row * 128 + ((ck ^ (row & 7)) * 16);
    }
    const __nv_bfloat16* bG[8]; uint32_t bOff[8];
#pragma unroll
    for (int i = 0; i < 8; i++) {
        const int id = tid + i * 256;
        const int row = id >> 3, ck = id & 7;
        bG[i] = WT + (size_t)row * K + ck * 8;
        bOff[i] = row * 128 + ((ck ^ (row & 7)) * 16);
    }

    const int aRow0 = wm * 32 + (lane & 15);
    const int aCkH = lane >> 4;
    const int bRow0 = wn * 64 + ((lane >> 4) & 1) * 8 + (lane & 7);
    const int bCkH = (lane >> 3) & 1;

    float acc[2][8][4];
#pragma unroll
    for (int i = 0; i < 2; i++)
#pragma unroll
        for (int j = 0; j < 8; j++)
#pragma unroll
            for (int k = 0; k < 4; k++) acc[i][j][k] = 0.f;

    const int Cs = K >> 6;
    const uint32_t STG = 40960;  // stage stride: A 8KB @0, B 32KB @8192

    // prologue: stage 0 (k=0), stage 1 (k=64)
#pragma unroll
    for (int i = 0; i < 2; i++) cpasync16(smBase + aOff[i], aG[i]);
#pragma unroll
    for (int i = 0; i < 8; i++) cpasync16(smBase + 8192 + bOff[i], bG[i]);
    asm volatile("cp.async.commit_group;" ::: "memory");
#pragma unroll
    for (int i = 0; i < 2; i++) cpasync16(smBase + STG + aOff[i], aG[i] + 64);
#pragma unroll
    for (int i = 0; i < 8; i++) cpasync16(smBase + STG + 8192 + bOff[i], bG[i] + 64);
    asm volatile("cp.async.commit_group;" ::: "memory");

    for (int c = 0; c < Cs; ++c) {
        if (c == Cs - 1) asm volatile("cp.async.wait_group 0;" ::: "memory");
        else             asm volatile("cp.async.wait_group 1;" ::: "memory");
        __syncthreads();

        const uint32_t sA = smBase + (uint32_t)(c & 1) * STG;
        const uint32_t sB = sA + 8192;

#pragma unroll
        for (int ks = 0; ks < 4; ks++) {
            uint32_t af[2][4];
            uint32_t bfr[4][4];
#pragma unroll
            for (int mt = 0; mt < 2; mt++) {
                const int row = aRow0 + mt * 16;
                const int ck = ks * 2 + aCkH;
                ldsm_x4(af[mt][0], af[mt][1], af[mt][2], af[mt][3],
                        sA + row * 128 + ((ck ^ (row & 7)) * 16));
            }
#pragma unroll
            for (int np = 0; np < 4; np++) {
                const int row = bRow0 + np * 16;
                const int ck = ks * 2 + bCkH;
                ldsm_x4(bfr[np][0], bfr[np][1], bfr[np][2], bfr[np][3],
                        sB + row * 128 + ((ck ^ (row & 7)) * 16));
            }
#pragma unroll
            for (int mt = 0; mt < 2; mt++)
#pragma unroll
                for (int nt = 0; nt < 8; nt++)
                    mma_bf16(acc[mt][nt], af[mt], &bfr[nt >> 1][(nt & 1) * 2]);
        }
        __syncthreads();

        if (c + 2 < Cs) {
            const int k0 = (c + 2) << 6;
            const uint32_t dst = smBase + (uint32_t)(c & 1) * STG;
#pragma unroll
            for (int i = 0; i < 2; i++) cpasync16(dst + aOff[i], aG[i] + k0);
#pragma unroll
            for (int i = 0; i < 8; i++) cpasync16(dst + 8192 + bOff[i], bG[i] + k0);
            asm volatile("cp.async.commit_group;" ::: "memory");
        }
    }

    // ---- stage C tile (64x256 fp32) to smem with bias + residual ----
    {
        const int rb = wm * 32 + (lane >> 2);
        const int cb = wn * 64 + (lane & 3) * 2;
#pragma unroll
        for (int mt = 0; mt < 2; mt++) {
#pragma unroll
            for (int nt = 0; nt < 8; nt++) {
                const int col = cb + nt * 8;
                const float bx = bias[col], by = bias[col + 1];
#pragma unroll
                for (int half = 0; half < 2; half++) {
                    const int r = rb + mt * 16 + half * 8;
                    const float* rp = res + (size_t)(bm + r) * 256 + col;
                    smF[r * 256 + col]     = acc[mt][nt][half * 2 + 0] + bx + rp[0];
                    smF[r * 256 + col + 1] = acc[mt][nt][half * 2 + 1] + by + rp[1];
                }
            }
        }
    }
    __syncthreads();

    // ---- LayerNorm: warp wid handles rows wid*8 .. wid*8+7 ----
#pragma unroll
    for (int r8 = 0; r8 < 8; r8++) {
        const int r = wid * 8 + r8;
        const float4* row4 = (const float4*)(smF + r * 256);
        const float4 X0 = row4[lane * 2], X1 = row4[lane * 2 + 1];

        float s = X0.x + X0.y + X0.z + X0.w + X1.x + X1.y + X1.z + X1.w;
#pragma unroll
        for (int o = 16; o; o >>= 1) s += __shfl_xor_sync(0xffffffffu, s, o);
        const float mu = s * (1.f / 256.f);

        float4 d0, d1;
        d0.x = X0.x - mu; d0.y = X0.y - mu; d0.z = X0.z - mu; d0.w = X0.w - mu;
        d1.x = X1.x - mu; d1.y = X1.y - mu; d1.z = X1.z - mu; d1.w = X1.w - mu;
        float v = d0.x*d0.x + d0.y*d0.y + d0.z*d0.z + d0.w*d0.w
                + d1.x*d1.x + d1.y*d1.y + d1.z*d1.z + d1.w*d1.w;
#pragma unroll
        for (int o = 16; o; o >>= 1) v += __shfl_xor_sync(0xffffffffu, v, o);
        const float rstd = rsqrtf(v * (1.f / 256.f) + 1e-5f);

        const float4 g0 = ((const float4*)gamma)[lane * 2], g1 = ((const float4*)gamma)[lane * 2 + 1];
        const float4 b0 = ((const float4*)beta)[lane * 2],  b1 = ((const float4*)beta)[lane * 2 + 1];
        float4 y0, y1;
        y0.x = d0.x * rstd * g0.x + b0.x; y0.y = d0.y * rstd * g0.y + b0.y;
        y0.z = d0.z * rstd * g0.z + b0.z; y0.w = d0.w * rstd * g0.w + b0.w;
        y1.x = d1.x * rstd * g1.x + b1.x; y1.y = d1.y * rstd * g1.y + b1.y;
        y1.z = d1.z * rstd * g1.z + b1.z; y1.w = d1.w * rstd * g1.w + b1.w;

        float4* o4 = (float4*)(outF + (size_t)(bm + r) * 256);
        o4[lane * 2] = y0; o4[lane * 2 + 1] = y1;
        if (outB) {
            __nv_bfloat162* r2 = (__nv_bfloat162*)(outB + (size_t)(bm + r) * 256) + lane * 4;
            r2[0] = __floats2bfloat162_rn(y0.x, y0.y);
            r2[1] = __floats2bfloat162_rn(y0.z, y0.w);
            r2[2] = __floats2bfloat162_rn(y1.x, y1.y);
            r2[3] = __floats2bfloat162_rn(y1.z, y1.w);
        }
    }
}

// ---------------- fused prep + weight transposes (single launch) ----------------
__device__ __forceinline__ void tr_tile(
    const float* __restrict__ W, __nv_bfloat16* __restrict__ WT,
    int K, int N, int kt, int nt, float (*tile)[33])
{
    const int k0 = kt * 32, n0 = nt * 32;
    const int tx = threadIdx.x & 31, ty = threadIdx.x >> 5;
#pragma unroll
    for (int r = 0; r < 4; r++)
        tile[ty + r * 8][tx] = W[(size_t)(k0 + ty + r * 8) * N + n0 + tx];
    __syncthreads();
#pragma unroll
    for (int r = 0; r < 4; r++)
        WT[(size_t)(n0 + ty + r * 8) * K + k0 + tx] = __float2bfloat16_rn(tile[tx][ty + r * 8]);
}

#define PREP_BLOCKS (M_ROWS * D_MODEL / 4 / 256)   // 10880

__global__ void __launch_bounds__(256) prep_all(
    const float* __restrict__ src, const float* __restrict__ pos,
    __nv_bfloat16* __restrict__ srcb, __nv_bfloat16* __restrict__ qsumb,
    const float* __restrict__ Wval, const float* __restrict__ Woff,
    const float* __restrict__ Wattn, const float* __restrict__ Wout,
    const float* __restrict__ W1, const float* __restrict__ W2,
    __nv_bfloat16* __restrict__ WvalT, __nv_bfloat16* __restrict__ WoaT,
    __nv_bfloat16* __restrict__ WoutT, __nv_bfloat16* __restrict__ W1T,
    __nv_bfloat16* __restrict__ W2T)
{
    __shared__ float tile[32][33];
    const int bx = blockIdx.x;
    if (bx < PREP_BLOCKS) {
        const int i = bx * 256 + threadIdx.x;
        float4 s = ((const float4*)src)[i];
        float4 p = ((const float4*)pos)[i];
        __nv_bfloat162* sb = (__nv_bfloat162*)srcb + i * 2;
        __nv_bfloat162* qb = (__nv_bfloat162*)qsumb + i * 2;
        sb[0] = __floats2bfloat162_rn(s.x, s.y);
        sb[1] = __floats2bfloat162_rn(s.z, s.w);
        qb[0] = __floats2bfloat162_rn(s.x + p.x, s.y + p.y);
        qb[1] = __floats2bfloat162_rn(s.z + p.z, s.w + p.w);
        return;
    }
    const int t = bx - PREP_BLOCKS;
    if (t < 64)       tr_tile(Wval, WvalT, 256, 256, t >> 3, t & 7, tile);
    else if (t < 128) { const int u = t - 64;  tr_tile(Woff, WoaT, 256, 256, u >> 3, u & 7, tile); }
    else if (t < 160) { const int u = t - 128; tr_tile(Wattn, WoaT + 256 * 256, 256, 128, u >> 2, u & 3, tile); }
    else if (t < 224) { const int u = t - 160; tr_tile(Wout, WoutT, 256, 256, u >> 3, u & 7, tile); }
    else if (t < 480) { const int u = t - 224; tr_tile(W1, W1T, 256, 1024, u >> 5, u & 31, tile); }
    else              { const int u = t - 480; tr_tile(W2, W2T, 1024, 256, u >> 3, u & 7, tile); }
}

// ---------------- sampler: warp per (bq, head-pair); bf16x2 channels ----------------
__global__ void __launch_bounds__(256) sample_bf(
    const __nv_bfloat16* __restrict__ value,
    const float* __restrict__ oa,
    const float* __restrict__ refp, __nv_bfloat16* __restrict__ samp)
{
    const int warp_id = (blockIdx.x * blockDim.x + threadIdx.x) >> 5;
    const int lane = threadIdx.x & 31;
    const int hh = warp_id & 3;
    const int bq = warp_id >> 2;
    const int b  = (bq >= LQ) ? 1 : 0;
    const int h  = hh * 2 + (lane >> 4);
    const int li = lane & 15;
    const int hsel = lane & 16;

    const float* al = oa + (size_t)bq * 384 + 256 + h * 16;
    const float logit = al[li];
    float mx = logit;
#pragma unroll
    for (int o = 8; o; o >>= 1) mx = fmaxf(mx, __shfl_xor_sync(0xffffffffu, mx, o));
    const float e = __expf(logit - mx);
    float se = e;
#pragma unroll
    for (int o = 8; o; o >>= 1) se += __shfl_xor_sync(0xffffffffu, se, o);
    const float inv_se = 1.f / se;

    int cip; uint32_t wpk01, wpk23;
    {
        const int lvl = li >> 2;
        const int Ww = 128 >> lvl;
        const float fW = (float)Ww;
        const float invW = 1.f / fW;
        const int st = c_ST[lvl];

        const float* op = oa + (size_t)bq * 384 + h * 32;
        const float ox = op[li * 2 + 0];
        const float oy = op[li * 2 + 1];
        const float* rp = refp + (size_t)bq * 8;
        const float rx = rp[lvl * 2 + 0];
        const float ry = rp[lvl * 2 + 1];

        const float x = (rx + ox * invW) * fW - 0.5f;
        const float y = (ry + oy * invW) * fW - 0.5f;
        const float x0f = floorf(x), y0f = floorf(y);
        const int x0 = (int)x0f, y0 = (int)y0f;
        const float wx1 = x - x0f, wy1 = y - y0f;
        const float wx0 = 1.f - wx1, wy0 = 1.f - wy1;

        const float w = e * inv_se;
        const float vx0 = (x0 >= 0 && x0 < Ww) ? 1.f : 0.f;
        const float vx1 = (x0 + 1 >= 0 && x0 + 1 < Ww) ? 1.f : 0.f;
        const float vy0 = (y0 >= 0 && y0 < Ww) ? 1.f : 0.f;
        const float vy1 = (y0 + 1 >= 0 && y0 + 1 < Ww) ? 1.f : 0.f;

        const float cw0 = w * (wx0 * wy0) * (vx0 * vy0);
        const float cw1 = w * (wx1 * wy0) * (vx1 * vy0);
        const float cw2 = w * (wx0 * wy1) * (vx0 * vy1);
        const float cw3 = w * (wx1 * wy1) * (vx1 * vy1);

        const int xc0 = min(max(x0, 0), Ww - 1);
        const int xc1 = min(max(x0 + 1, 0), Ww - 1);
        const int yc0 = min(max(y0, 0), Ww - 1);
        const int yc1 = min(max(y0 + 1, 0), Ww - 1);
        cip = ((st + yc0 * Ww + xc0) << 2) | ((yc1 - yc0) << 1) | (xc1 - xc0);

        __half2 ha = __floats2half2_rn(cw0, cw1);
        __half2 hb2 = __floats2half2_rn(cw2, cw3);
        wpk01 = *(uint32_t*)&ha;
        wpk23 = *(uint32_t*)&hb2;
    }

    const __nv_bfloat162* v2 = (const __nv_bfloat162*)value
        + (size_t)b * LQ * 128 + h * 16 + li;
    float ax0 = 0.f, ay0 = 0.f, ax1 = 0.f, ay1 = 0.f;
#pragma unroll
    for (int p = 0; p < 16; p++) {
        const int src = hsel | p;
        const int pk = __shfl_sync(0xffffffffu, cip, src);
        const uint32_t wa = __shfl_sync(0xffffffffu, wpk01, src);
        const uint32_t wb = __shfl_sync(0xffffffffu, wpk23, src);
        const int tok = pk >> 2;
        const int dx  = pk & 1;
        const int dyW = ((pk >> 1) & 1) * (128 >> (p >> 2));

        const __nv_bfloat162 r00 = __ldg(v2 + (size_t)tok * 128);
        const __nv_bfloat162 r10 = __ldg(v2 + (size_t)(tok + dx) * 128);
        const __nv_bfloat162 r01 = __ldg(v2 + (size_t)(tok + dyW) * 128);
        const __nv_bfloat162 r11 = __ldg(v2 + (size_t)(tok + dyW + dx) * 128);

        const float2 w01 = __half22float2(*(const __half2*)&wa);
        const float2 w23 = __half22float2(*(const __half2*)&wb);
        float2 f;
        f = __bfloat1622float2(r00); ax0 += w01.x * f.x; ay0 += w01.x * f.y;
        f = __bfloat1622float2(r10); ax1 += w01.y * f.x; ay1 += w01.y * f.y;
        f = __bfloat1622float2(r01); ax0 += w23.x * f.x; ay0 += w23.x * f.y;
        f = __bfloat1622float2(r11); ax1 += w23.y * f.x; ay1 += w23.y * f.y;
    }
    ((__nv_bfloat162*)(samp + (size_t)bq * 256 + h * 32))[li] =
        __floats2bfloat162_rn(ax0 + ax1, ay0 + ay1);
}

// ---------------- launch ----------------
extern "C" void kernel_launch(void* const* d_in, const int* in_sizes, int n_in,
                              void* d_out, int out_size)
{
    const float* src    = (const float*)d_in[0];
    const float* pos    = (const float*)d_in[1];
    const float* refp   = (const float*)d_in[2];
    const float* W_off  = (const float*)d_in[3];
    const float* b_off  = (const float*)d_in[4];
    const float* W_attn = (const float*)d_in[5];
    const float* b_attn = (const float*)d_in[6];
    const float* W_val  = (const float*)d_in[7];
    const float* b_val  = (const float*)d_in[8];
    const float* W_out  = (const float*)d_in[9];
    const float* b_out  = (const float*)d_in[10];
    const float* ln1_g  = (const float*)d_in[11];
    const float* ln1_b  = (const float*)d_in[12];
    const float* W1     = (const float*)d_in[13];
    const float* b1     = (const float*)d_in[14];
    const float* W2     = (const float*)d_in[15];
    const float* b2     = (const float*)d_in[16];
    const float* ln2_g  = (const float*)d_in[17];
    const float* ln2_b  = (const float*)d_in[18];
    float* out = (float*)d_out;

    __nv_bfloat16 *p_srcb, *p_qsumb, *p_value, *p_samp, *p_hb, *p_ffn;
    __nv_bfloat16 *p_WvalT, *p_WoaT, *p_WoutT, *p_W1T, *p_W2T;
    float *p_oa, *p_h;
    cudaGetSymbolAddress((void**)&p_srcb,  g_srcb);
    cudaGetSymbolAddress((void**)&p_qsumb, g_qsumb);
    cudaGetSymbolAddress((void**)&p_value, g_value);
    cudaGetSymbolAddress((void**)&p_oa,    g_oa);
    cudaGetSymbolAddress((void**)&p_samp,  g_samp);
    cudaGetSymbolAddress((void**)&p_h,     g_h);
    cudaGetSymbolAddress((void**)&p_hb,    g_hb);
    cudaGetSymbolAddress((void**)&p_ffn,   g_ffn);
    cudaGetSymbolAddress((void**)&p_WvalT, g_WvalT);
    cudaGetSymbolAddress((void**)&p_WoaT,  g_WoaT);
    cudaGetSymbolAddress((void**)&p_WoutT, g_WoutT);
    cudaGetSymbolAddress((void**)&p_W1T,   g_W1T);
    cudaGetSymbolAddress((void**)&p_W2T,   g_W2T);

    const int SMEM_GEMM = 3 * 32768;   // 96 KB
    const int SMEM_LN   = 2 * 40960;   // 80 KB (>= 64KB epilogue tile)
    cudaFuncSetAttribute(gemm_proj, cudaFuncAttributeMaxDynamicSharedMemorySize, SMEM_GEMM);
    cudaFuncSetAttribute(gemm_ffn,  cudaFuncAttributeMaxDynamicSharedMemorySize, SMEM_GEMM);
    cudaFuncSetAttribute(gemm_ln,   cudaFuncAttributeMaxDynamicSharedMemorySize, SMEM_LN);

    const int M = M_ROWS;
    const int MT = M / 128;   // 340
    const int MT64 = M / 64;  // 680

    // 0: prep + all weight transposes
    prep_all<<<PREP_BLOCKS + 736, 256>>>(src, pos, p_srcb, p_qsumb,
        W_val, W_off, W_attn, W_out, W1, W2,
        p_WvalT, p_WoaT, p_WoutT, p_W1T, p_W2T);
    // 1: value + oa projections (merged)
    gemm_proj<<<dim3(5, MT), 256, SMEM_GEMM>>>(
        p_srcb, p_qsumb, p_WvalT, p_WoaT, b_val, b_off, b_attn, p_value, p_oa);
    // 2: deformable sampling
    sample_bf<<<M / 2, 256>>>(p_value, p_oa, refp, p_samp);
    // 3: t1 = samp @ W_out + b_out + src ; h = LN1(t1) (+ bf16 copy hb)
    gemm_ln<<<MT64, 256, SMEM_LN>>>(
        p_samp, p_WoutT, b_out, src, ln1_g, ln1_b, p_h, p_hb, 256);
    // 4: ffn = relu(h @ W1 + b1)  (bf16)
    gemm_ffn<<<dim3(8, MT), 256, SMEM_GEMM>>>(p_hb, p_W1T, b1, p_ffn);
    // 5: t2 = ffn @ W2 + b2 + h ; out = LN2(t2)   <- ncu -s 5 -c 1
    gemm_ln<<<MT64, 256, SMEM_LN>>>(
        p_ffn, p_W2T, b2, p_h, ln2_g, ln2_b, out, nullptr, 1024);
}